// round 7
// baseline (speedup 1.0000x reference)
#include <cuda_runtime.h>
#include <cstdint>

// VanillaRNN on GB300 — Round 6: tf32 mma.sync + ldmatrix fragment feeding.
//
//   new_state = ReLU(X@W_in^T + state@W_rec^T + b_in + b_rec)  [8192,4096]
//   out       = ReLU(new_state@W_out^T + b_out)                [8192,1024]
// d_out = (out, new_state); new_state region reused as GEMM3 input.
//
// BM=BN=128, BK=32, 128 threads (4 warps 2x2), warp tile 64x64,
// 3-stage cp.async pipeline. Fragments fed via ldmatrix.m8n8.x4.b16:
// an 8x8 fp32 tile == 8x16 b16 tile; x4 lane mapping reproduces the
// m16n8k8 tf32 fragment exactly (4 LDSM for A + 4 for B per k8 step,
// replacing 32 scalar LDS). Fragment regs double-buffered across ks.
// Inputs rounded to tf32-RN via +0x1000 before MMA.

#define BM 128
#define BN 128
#define BK 32
#define STAGES 3
#define SROW 36                         // floats per smem row (32 + 4 pad)
#define TILE_FLOATS (BM * SROW)         // 4608 per operand
#define STAGE_FLOATS (2 * TILE_FLOATS)  // 9216
#define STAGE_BYTES  (STAGE_FLOATS * 4) // 36864
#define SMEM_BYTES   (STAGES * STAGE_BYTES) // 110592

__device__ __forceinline__ uint32_t s2u(const void* p) {
    uint32_t a;
    asm("{ .reg .u64 t; cvta.to.shared.u64 t, %1; cvt.u32.u64 %0, t; }" : "=r"(a) : "l"(p));
    return a;
}

#define CP16(dst, src) \
    asm volatile("cp.async.cg.shared.global [%0], [%1], 16;" :: "r"(dst), "l"(src))
#define CP_COMMIT() asm volatile("cp.async.commit_group;" ::: "memory")
#define CP_WAIT(N)  asm volatile("cp.async.wait_group %0;" :: "n"(N) : "memory")

// round fp32 bits to tf32 nearest: +half-ulp(13-bit) then HW truncation
__device__ __forceinline__ uint32_t rnd(uint32_t u) { return u + 0x1000u; }

#define LDSM4(r0, r1, r2, r3, addr)                                            \
    asm volatile("ldmatrix.sync.aligned.m8n8.x4.shared.b16 {%0,%1,%2,%3}, [%4];" \
                 : "=r"(r0), "=r"(r1), "=r"(r2), "=r"(r3) : "r"(addr))

#define MMA_TF32(ac, a0, a1, a2, a3, b0, b1)                                   \
    asm volatile(                                                              \
        "mma.sync.aligned.m16n8k8.row.col.f32.tf32.tf32.f32 "                  \
        "{%0,%1,%2,%3}, {%4,%5,%6,%7}, {%8,%9}, {%0,%1,%2,%3};"                \
        : "+f"((ac)[0]), "+f"((ac)[1]), "+f"((ac)[2]), "+f"((ac)[3])           \
        : "r"(a0), "r"(a1), "r"(a2), "r"(a3), "r"(b0), "r"(b1))

__global__ void __launch_bounds__(128, 2) rnn_gemm_mma(
    const float* __restrict__ A1, int lda1,
    const float* __restrict__ B1, int ldb1, int n1,
    const float* __restrict__ A2, int lda2,
    const float* __restrict__ B2, int ldb2, int n2,
    const float* __restrict__ bias1, const float* __restrict__ bias2,
    float* __restrict__ C, int ldc)
{
    extern __shared__ __align__(16) float smem[];
    const uint32_t sbase = s2u(smem);

    const int tid  = threadIdx.x;
    const int warp = tid >> 5;
    const int lane = tid & 31;
    const int tg   = lane & 3;    // thread in group (0..3)
    const int g    = lane >> 2;   // group id (0..7)
    const int wm   = warp >> 1;   // warp m index (0..1)
    const int wn   = warp & 1;    // warp n index (0..1)

    const int rowBase = blockIdx.y * BM;
    const int colBase = blockIdx.x * BN;
    const int niters  = n1 + n2;

    // per-lane ldmatrix offset: lanes 0-15 -> rows 0..15 (matrices 0/1),
    // lanes 16-31 -> same rows, fp32 col +4 (matrices 2/3)
    const uint32_t laneOff = (((uint32_t)(lane & 15)) * SROW + ((lane >> 4) << 2)) * 4;

    float acc[4][8][4];
#pragma unroll
    for (int i = 0; i < 4; i++)
#pragma unroll
        for (int j = 0; j < 8; j++)
#pragma unroll
            for (int v = 0; v < 4; v++) acc[i][j][v] = 0.0f;

    // ---- stage loader: each thread fills one A row + one B row (8x16B each)
    auto load_stage = [&](int j, int s) {
        const float* Ab; const float* Bb; int lda, ldb, ko;
        if (j < n1) { Ab = A1; Bb = B1; lda = lda1; ldb = ldb1; ko = j * BK; }
        else        { Ab = A2; Bb = B2; lda = lda2; ldb = ldb2; ko = (j - n1) * BK; }
        const uint32_t stA = sbase + s * STAGE_BYTES + tid * (SROW * 4);
        const uint32_t stB = stA + TILE_FLOATS * 4;
        const float* ga = Ab + (size_t)(rowBase + tid) * lda + ko;
        const float* gb = Bb + (size_t)(colBase + tid) * ldb + ko;
#pragma unroll
        for (int c = 0; c < 8; c++) CP16(stA + c * 16, ga + c * 4);
#pragma unroll
        for (int c = 0; c < 8; c++) CP16(stB + c * 16, gb + c * 4);
    };

    // fragment loader for one k8 step: 4 LDSM.x4 for A, 4 for B
    auto load_frags = [&](int s, int ks, uint32_t* fa, uint32_t* fb) {
        const uint32_t base  = sbase + s * STAGE_BYTES + (uint32_t)(ks * 8) * 4 + laneOff;
        const uint32_t baseA = base + (uint32_t)(wm * 64) * (SROW * 4);
        const uint32_t baseB = base + TILE_FLOATS * 4 + (uint32_t)(wn * 64) * (SROW * 4);
#pragma unroll
        for (int i = 0; i < 4; i++)
            LDSM4(fa[4 * i], fa[4 * i + 1], fa[4 * i + 2], fa[4 * i + 3],
                  baseA + (uint32_t)(i * 16) * (SROW * 4));
#pragma unroll
        for (int jp = 0; jp < 4; jp++)
            LDSM4(fb[4 * jp], fb[4 * jp + 1], fb[4 * jp + 2], fb[4 * jp + 3],
                  baseB + (uint32_t)(jp * 16) * (SROW * 4));
    };

    // ---- prologue: 2 stages in flight ----
    load_stage(0, 0); CP_COMMIT();
    load_stage(1, 1); CP_COMMIT();

    uint32_t fa[2][16], fb[2][16];

    // ---- main loop ----
#pragma unroll 1
    for (int it = 0; it < niters; ++it) {
        const int s = it % STAGES;
        if (it < niters - 1) { CP_WAIT(1); } else { CP_WAIT(0); }
        __syncthreads();

        if (it + 2 < niters) { load_stage(it + 2, (it + 2) % STAGES); CP_COMMIT(); }

        load_frags(s, 0, fa[0], fb[0]);

#pragma unroll
        for (int ks = 0; ks < 4; ks++) {
            const int cur = ks & 1;
            if (ks < 3) load_frags(s, ks + 1, fa[cur ^ 1], fb[cur ^ 1]);

            uint32_t ra[16], rb[16];
#pragma unroll
            for (int q = 0; q < 16; q++) { ra[q] = rnd(fa[cur][q]); rb[q] = rnd(fb[cur][q]); }

#pragma unroll
            for (int i = 0; i < 4; i++)
#pragma unroll
                for (int j = 0; j < 8; j++) {
                    const int jp = j >> 1, jo = j & 1;
                    MMA_TF32(acc[i][j],
                             ra[4 * i], ra[4 * i + 1], ra[4 * i + 2], ra[4 * i + 3],
                             rb[4 * jp + jo], rb[4 * jp + 2 + jo]);
                }
        }
    }

    // ---- epilogue: bias + ReLU, float2 stores ----
    float2 bv[8];
#pragma unroll
    for (int j = 0; j < 8; j++) {
        const int c = colBase + wn * 64 + j * 8 + 2 * tg;
        float2 b = *(const float2*)(bias1 + c);
        if (bias2) {
            float2 b2 = *(const float2*)(bias2 + c);
            b.x += b2.x; b.y += b2.y;
        }
        bv[j] = b;
    }
#pragma unroll
    for (int i = 0; i < 4; i++) {
        const int r0 = rowBase + wm * 64 + i * 16 + g;
#pragma unroll
        for (int j = 0; j < 8; j++) {
            const int c = colBase + wn * 64 + j * 8 + 2 * tg;
            float2 v0, v1;
            v0.x = fmaxf(acc[i][j][0] + bv[j].x, 0.0f);
            v0.y = fmaxf(acc[i][j][1] + bv[j].y, 0.0f);
            v1.x = fmaxf(acc[i][j][2] + bv[j].x, 0.0f);
            v1.y = fmaxf(acc[i][j][3] + bv[j].y, 0.0f);
            *(float2*)&C[(size_t)r0 * ldc + c]       = v0;
            *(float2*)&C[(size_t)(r0 + 8) * ldc + c] = v1;
        }
    }
}

extern "C" void kernel_launch(void* const* d_in, const int* in_sizes, int n_in,
                              void* d_out, int out_size)
{
    (void)in_sizes; (void)n_in; (void)out_size;
    const int B_ = 8192, DIN = 1024, H_ = 4096, DO_ = 1024;

    const float* X     = (const float*)d_in[0];
    const float* state = (const float*)d_in[1];
    const float* W_in  = (const float*)d_in[2];
    const float* b_in  = (const float*)d_in[3];
    const float* W_rec = (const float*)d_in[4];
    const float* b_rec = (const float*)d_in[5];
    const float* W_out = (const float*)d_in[6];
    const float* b_out = (const float*)d_in[7];

    float* out       = (float*)d_out;                     // [B, D_OUT]
    float* new_state = (float*)d_out + (size_t)B_ * DO_;  // [B, H]

    static int inited = 0;
    if (!inited) {
        cudaFuncSetAttribute(rnn_gemm_mma,
                             cudaFuncAttributeMaxDynamicSharedMemorySize, SMEM_BYTES);
        inited = 1;
    }

    // GEMM1+2 fused along K: new_state = ReLU(X@W_in^T + state@W_rec^T + b)
    {
        dim3 grid(H_ / BN, B_ / BM);   // (32, 64)
        rnn_gemm_mma<<<grid, 128, SMEM_BYTES>>>(
            X, DIN, W_in, DIN, DIN / BK,
            state, H_, W_rec, H_, H_ / BK,
            b_in, b_rec, new_state, H_);
    }
    // GEMM3: out = ReLU(new_state@W_out^T + b_out)
    {
        dim3 grid(DO_ / BN, B_ / BM);  // (8, 64)
        rnn_gemm_mma<<<grid, 128, SMEM_BYTES>>>(
            new_state, H_, W_out, H_, H_ / BK,
            nullptr, 0, nullptr, 0, 0,
            b_out, nullptr, out, DO_);
    }
}

// round 8
// speedup vs baseline: 1.5453x; 1.5453x over previous
#include <cuda_runtime.h>
#include <cstdint>

// VanillaRNN on GB300 — Round 7: tf32 mma.sync + ldmatrix, occupancy fix.
//
//   new_state = ReLU(X@W_in^T + state@W_rec^T + b_in + b_rec)  [8192,4096]
//   out       = ReLU(new_state@W_out^T + b_out)                [8192,1024]
// d_out = (out, new_state); new_state region reused as GEMM3 input.
//
// BM=BN=128, BK=32, 256 threads (8 warps, 2x4), warp tile 64x32,
// acc = 64 f32/thread -> <=128 regs -> 2 CTAs/SM -> 16 warps/SM.
// 3-stage cp.async pipeline; fragments via ldmatrix.m8n8.x4.b16
// (mapping verified in R6: 8x8 fp32 tile == 8x16 b16 tile), single-buffered,
// tf32-RN rounding (+0x1000) applied in place.

#define BM 128
#define BN 128
#define BK 32
#define STAGES 3
#define SROW 36                         // floats per smem row (32 + 4 pad)
#define TILE_FLOATS (BM * SROW)         // 4608 per operand
#define STAGE_FLOATS (2 * TILE_FLOATS)  // 9216
#define STAGE_BYTES  (STAGE_FLOATS * 4) // 36864
#define SMEM_BYTES   (STAGES * STAGE_BYTES) // 110592

__device__ __forceinline__ uint32_t s2u(const void* p) {
    uint32_t a;
    asm("{ .reg .u64 t; cvta.to.shared.u64 t, %1; cvt.u32.u64 %0, t; }" : "=r"(a) : "l"(p));
    return a;
}

#define CP16(dst, src) \
    asm volatile("cp.async.cg.shared.global [%0], [%1], 16;" :: "r"(dst), "l"(src))
#define CP_COMMIT() asm volatile("cp.async.commit_group;" ::: "memory")
#define CP_WAIT(N)  asm volatile("cp.async.wait_group %0;" :: "n"(N) : "memory")

#define LDSM4(r0, r1, r2, r3, addr)                                            \
    asm volatile("ldmatrix.sync.aligned.m8n8.x4.shared.b16 {%0,%1,%2,%3}, [%4];" \
                 : "=r"(r0), "=r"(r1), "=r"(r2), "=r"(r3) : "r"(addr))

#define MMA_TF32(ac, a0, a1, a2, a3, b0, b1)                                   \
    asm volatile(                                                              \
        "mma.sync.aligned.m16n8k8.row.col.f32.tf32.tf32.f32 "                  \
        "{%0,%1,%2,%3}, {%4,%5,%6,%7}, {%8,%9}, {%0,%1,%2,%3};"                \
        : "+f"((ac)[0]), "+f"((ac)[1]), "+f"((ac)[2]), "+f"((ac)[3])           \
        : "r"(a0), "r"(a1), "r"(a2), "r"(a3), "r"(b0), "r"(b1))

__global__ void __launch_bounds__(256, 2) rnn_gemm_mma(
    const float* __restrict__ A1, int lda1,
    const float* __restrict__ B1, int ldb1, int n1,
    const float* __restrict__ A2, int lda2,
    const float* __restrict__ B2, int ldb2, int n2,
    const float* __restrict__ bias1, const float* __restrict__ bias2,
    float* __restrict__ C, int ldc)
{
    extern __shared__ __align__(16) float smem[];
    const uint32_t sbase = s2u(smem);

    const int tid  = threadIdx.x;
    const int warp = tid >> 5;
    const int lane = tid & 31;
    const int tg   = lane & 3;    // thread in group (0..3)
    const int g    = lane >> 2;   // group id (0..7)
    const int wm   = warp >> 2;   // warp m index (0..1), tile rows wm*64..+64
    const int wn   = warp & 3;    // warp n index (0..3), tile cols wn*32..+32

    const int rowBase = blockIdx.y * BM;
    const int colBase = blockIdx.x * BN;
    const int niters  = n1 + n2;

    // ldmatrix lane offset: lanes 0-15 -> rows 0..15; lanes 16-31 -> +4 fp32 cols
    const uint32_t laneOff = (((uint32_t)(lane & 15)) * SROW + ((lane >> 4) << 2)) * 4;

    float acc[4][4][4];
#pragma unroll
    for (int i = 0; i < 4; i++)
#pragma unroll
        for (int j = 0; j < 4; j++)
#pragma unroll
            for (int v = 0; v < 4; v++) acc[i][j][v] = 0.0f;

    // ---- stage loader: 256 threads, one 128B row each (A rows 0-127, B rows 128-255)
    auto load_stage = [&](int j, int s) {
        const float* Ab; const float* Bb; int lda, ldb, ko;
        if (j < n1) { Ab = A1; Bb = B1; lda = lda1; ldb = ldb1; ko = j * BK; }
        else        { Ab = A2; Bb = B2; lda = lda2; ldb = ldb2; ko = (j - n1) * BK; }
        const int r = tid & 127;
        const bool isB = tid >= 128;
        const float* gsrc = isB ? (Bb + (size_t)(colBase + r) * ldb + ko)
                                : (Ab + (size_t)(rowBase + r) * lda + ko);
        const uint32_t st = sbase + s * STAGE_BYTES + (isB ? TILE_FLOATS * 4 : 0)
                          + r * (SROW * 4);
#pragma unroll
        for (int c = 0; c < 8; c++) CP16(st + c * 16, gsrc + c * 4);
    };

    // ---- prologue ----
    load_stage(0, 0); CP_COMMIT();
    load_stage(1, 1); CP_COMMIT();

    // ---- main loop ----
#pragma unroll 1
    for (int it = 0; it < niters; ++it) {
        const int s = it % STAGES;
        if (it < niters - 1) { CP_WAIT(1); } else { CP_WAIT(0); }
        __syncthreads();

        if (it + 2 < niters) { load_stage(it + 2, (it + 2) % STAGES); CP_COMMIT(); }

        const uint32_t stA = sbase + s * STAGE_BYTES + (uint32_t)(wm * 64) * (SROW * 4);
        const uint32_t stB = sbase + s * STAGE_BYTES + TILE_FLOATS * 4
                           + (uint32_t)(wn * 32) * (SROW * 4);

#pragma unroll
        for (int ks = 0; ks < 4; ks++) {
            const uint32_t ko = (uint32_t)(ks * 8) * 4 + laneOff;
            uint32_t fa[16], fb[8];
#pragma unroll
            for (int i = 0; i < 4; i++)
                LDSM4(fa[4 * i], fa[4 * i + 1], fa[4 * i + 2], fa[4 * i + 3],
                      stA + ko + (uint32_t)(i * 16) * (SROW * 4));
#pragma unroll
            for (int jp = 0; jp < 2; jp++)
                LDSM4(fb[4 * jp], fb[4 * jp + 1], fb[4 * jp + 2], fb[4 * jp + 3],
                      stB + ko + (uint32_t)(jp * 16) * (SROW * 4));

            // round to tf32-nearest in place
#pragma unroll
            for (int q = 0; q < 16; q++) fa[q] += 0x1000u;
#pragma unroll
            for (int q = 0; q < 8; q++)  fb[q] += 0x1000u;

#pragma unroll
            for (int i = 0; i < 4; i++)
#pragma unroll
                for (int j = 0; j < 4; j++) {
                    const int jp = j >> 1, jo = j & 1;
                    MMA_TF32(acc[i][j],
                             fa[4 * i], fa[4 * i + 1], fa[4 * i + 2], fa[4 * i + 3],
                             fb[4 * jp + jo], fb[4 * jp + 2 + jo]);
                }
        }
    }

    // ---- epilogue: bias + ReLU, float2 stores ----
    float2 bv[4];
#pragma unroll
    for (int j = 0; j < 4; j++) {
        const int c = colBase + wn * 32 + j * 8 + 2 * tg;
        float2 b = *(const float2*)(bias1 + c);
        if (bias2) {
            float2 b2 = *(const float2*)(bias2 + c);
            b.x += b2.x; b.y += b2.y;
        }
        bv[j] = b;
    }
#pragma unroll
    for (int i = 0; i < 4; i++) {
        const int r0 = rowBase + wm * 64 + i * 16 + g;
#pragma unroll
        for (int j = 0; j < 4; j++) {
            const int c = colBase + wn * 32 + j * 8 + 2 * tg;
            float2 v0, v1;
            v0.x = fmaxf(acc[i][j][0] + bv[j].x, 0.0f);
            v0.y = fmaxf(acc[i][j][1] + bv[j].y, 0.0f);
            v1.x = fmaxf(acc[i][j][2] + bv[j].x, 0.0f);
            v1.y = fmaxf(acc[i][j][3] + bv[j].y, 0.0f);
            *(float2*)&C[(size_t)r0 * ldc + c]       = v0;
            *(float2*)&C[(size_t)(r0 + 8) * ldc + c] = v1;
        }
    }
}

extern "C" void kernel_launch(void* const* d_in, const int* in_sizes, int n_in,
                              void* d_out, int out_size)
{
    (void)in_sizes; (void)n_in; (void)out_size;
    const int B_ = 8192, DIN = 1024, H_ = 4096, DO_ = 1024;

    const float* X     = (const float*)d_in[0];
    const float* state = (const float*)d_in[1];
    const float* W_in  = (const float*)d_in[2];
    const float* b_in  = (const float*)d_in[3];
    const float* W_rec = (const float*)d_in[4];
    const float* b_rec = (const float*)d_in[5];
    const float* W_out = (const float*)d_in[6];
    const float* b_out = (const float*)d_in[7];

    float* out       = (float*)d_out;                     // [B, D_OUT]
    float* new_state = (float*)d_out + (size_t)B_ * DO_;  // [B, H]

    static int inited = 0;
    if (!inited) {
        cudaFuncSetAttribute(rnn_gemm_mma,
                             cudaFuncAttributeMaxDynamicSharedMemorySize, SMEM_BYTES);
        inited = 1;
    }

    // GEMM1+2 fused along K: new_state = ReLU(X@W_in^T + state@W_rec^T + b)
    {
        dim3 grid(H_ / BN, B_ / BM);   // (32, 64)
        rnn_gemm_mma<<<grid, 256, SMEM_BYTES>>>(
            X, DIN, W_in, DIN, DIN / BK,
            state, H_, W_rec, H_, H_ / BK,
            b_in, b_rec, new_state, H_);
    }
    // GEMM3: out = ReLU(new_state@W_out^T + b_out)
    {
        dim3 grid(DO_ / BN, B_ / BM);  // (8, 64)
        rnn_gemm_mma<<<grid, 256, SMEM_BYTES>>>(
            new_state, H_, W_out, H_, H_ / BK,
            nullptr, 0, nullptr, 0, 0,
            b_out, nullptr, out, DO_);
    }
}

// round 9
// speedup vs baseline: 1.7372x; 1.1241x over previous
#include <cuda_runtime.h>
#include <cstdint>

// VanillaRNN on GB300 — Round 8: fatten warp tiles to fix the MIO:MMA ratio.
//
//   new_state = ReLU(X@W_in^T + state@W_rec^T + b_in + b_rec)  [8192,4096]
//   out       = ReLU(new_state@W_out^T + b_out)                [8192,1024]
// d_out = (out, new_state); new_state region reused as GEMM3 input.
//
// BM=128, BN=256, BK=32, 256 threads (8 warps, 2x4), warp tile 64x64:
// per warp-iter 32 LDSM.x4 + 12 LDGSTS feed 128 HMMA (2x the MMA:MIO of R7).
// 3-stage cp.async pipeline (stage 54KB, total 162KB -> 1 CTA/SM).
// Fragments via ldmatrix.m8n8.x4.b16 (mapping verified R6), single-buffered,
// tf32-RN rounding (+0x1000) in place.

#define BM 128
#define BN 256
#define BK 32
#define STAGES 3
#define SROW 36                           // floats per smem row (32 + 4 pad)
#define A_FLOATS (BM * SROW)              // 4608
#define B_FLOATS (BN * SROW)              // 9216
#define STAGE_FLOATS (A_FLOATS + B_FLOATS)  // 13824
#define STAGE_BYTES  (STAGE_FLOATS * 4)     // 55296
#define SMEM_BYTES   (STAGES * STAGE_BYTES) // 165888

__device__ __forceinline__ uint32_t s2u(const void* p) {
    uint32_t a;
    asm("{ .reg .u64 t; cvta.to.shared.u64 t, %1; cvt.u32.u64 %0, t; }" : "=r"(a) : "l"(p));
    return a;
}

#define CP16(dst, src) \
    asm volatile("cp.async.cg.shared.global [%0], [%1], 16;" :: "r"(dst), "l"(src))
#define CP_COMMIT() asm volatile("cp.async.commit_group;" ::: "memory")
#define CP_WAIT(N)  asm volatile("cp.async.wait_group %0;" :: "n"(N) : "memory")

#define LDSM4(r0, r1, r2, r3, addr)                                            \
    asm volatile("ldmatrix.sync.aligned.m8n8.x4.shared.b16 {%0,%1,%2,%3}, [%4];" \
                 : "=r"(r0), "=r"(r1), "=r"(r2), "=r"(r3) : "r"(addr))

#define MMA_TF32(ac, a0, a1, a2, a3, b0, b1)                                   \
    asm volatile(                                                              \
        "mma.sync.aligned.m16n8k8.row.col.f32.tf32.tf32.f32 "                  \
        "{%0,%1,%2,%3}, {%4,%5,%6,%7}, {%8,%9}, {%0,%1,%2,%3};"                \
        : "+f"((ac)[0]), "+f"((ac)[1]), "+f"((ac)[2]), "+f"((ac)[3])           \
        : "r"(a0), "r"(a1), "r"(a2), "r"(a3), "r"(b0), "r"(b1))

__global__ void __launch_bounds__(256) rnn_gemm_mma(
    const float* __restrict__ A1, int lda1,
    const float* __restrict__ B1, int ldb1, int n1,
    const float* __restrict__ A2, int lda2,
    const float* __restrict__ B2, int ldb2, int n2,
    const float* __restrict__ bias1, const float* __restrict__ bias2,
    float* __restrict__ C, int ldc)
{
    extern __shared__ __align__(16) float smem[];
    const uint32_t sbase = s2u(smem);

    const int tid  = threadIdx.x;
    const int warp = tid >> 5;
    const int lane = tid & 31;
    const int tg   = lane & 3;    // thread in group (0..3)
    const int g    = lane >> 2;   // group id (0..7)
    const int wm   = warp >> 2;   // warp m index (0..1), rows wm*64..+64
    const int wn   = warp & 3;    // warp n index (0..3), cols wn*64..+64

    const int rowBase = blockIdx.y * BM;
    const int colBase = blockIdx.x * BN;
    const int niters  = n1 + n2;

    // ldmatrix lane offset: lanes 0-15 -> rows 0..15; lanes 16-31 -> +4 fp32 cols
    const uint32_t laneOff = (((uint32_t)(lane & 15)) * SROW + ((lane >> 4) << 2)) * 4;

    float acc[4][8][4];
#pragma unroll
    for (int i = 0; i < 4; i++)
#pragma unroll
        for (int j = 0; j < 8; j++)
#pragma unroll
            for (int v = 0; v < 4; v++) acc[i][j][v] = 0.0f;

    // ---- stage loader: 384 rows (128 A + 256 B), 256 threads, 12 CP16 each
    auto load_stage = [&](int j, int s) {
        const float* Ab; const float* Bb; int lda, ldb, ko;
        if (j < n1) { Ab = A1; Bb = B1; lda = lda1; ldb = ldb1; ko = j * BK; }
        else        { Ab = A2; Bb = B2; lda = lda2; ldb = ldb2; ko = (j - n1) * BK; }
        const uint32_t base = sbase + s * STAGE_BYTES;

        // pass 1: full row per thread. tid<128 -> A row tid; else B row tid-128
        {
            const int r = tid & 127;
            const bool isB = tid >= 128;
            const float* gsrc = isB ? (Bb + (size_t)(colBase + r) * ldb + ko)
                                    : (Ab + (size_t)(rowBase + r) * lda + ko);
            const uint32_t st = base + (isB ? A_FLOATS * 4 : 0) + r * (SROW * 4);
#pragma unroll
            for (int c = 0; c < 8; c++) CP16(st + c * 16, gsrc + c * 4);
        }
        // pass 2: B rows 128..255, half row per thread
        {
            const int r = 128 + (tid >> 1);
            const int h = (tid & 1) * 16;   // float offset within row
            const float* gsrc = Bb + (size_t)(colBase + r) * ldb + ko + h;
            const uint32_t st = base + A_FLOATS * 4 + r * (SROW * 4) + h * 4;
#pragma unroll
            for (int c = 0; c < 4; c++) CP16(st + c * 16, gsrc + c * 4);
        }
    };

    // ---- prologue ----
    load_stage(0, 0); CP_COMMIT();
    load_stage(1, 1); CP_COMMIT();

    // ---- main loop ----
#pragma unroll 1
    for (int it = 0; it < niters; ++it) {
        const int s = it % STAGES;
        if (it < niters - 1) { CP_WAIT(1); } else { CP_WAIT(0); }
        __syncthreads();   // also protects ring reuse: stage (it+2)%3 == (it-1)%3

        if (it + 2 < niters) { load_stage(it + 2, (it + 2) % STAGES); CP_COMMIT(); }

        const uint32_t stA = sbase + s * STAGE_BYTES
                           + (uint32_t)(wm * 64) * (SROW * 4);
        const uint32_t stB = sbase + s * STAGE_BYTES + A_FLOATS * 4
                           + (uint32_t)(wn * 64) * (SROW * 4);

#pragma unroll
        for (int ks = 0; ks < 4; ks++) {
            const uint32_t ko = (uint32_t)(ks * 8) * 4 + laneOff;
            uint32_t fa[16], fb[16];
#pragma unroll
            for (int i = 0; i < 4; i++)
                LDSM4(fa[4 * i], fa[4 * i + 1], fa[4 * i + 2], fa[4 * i + 3],
                      stA + ko + (uint32_t)(i * 16) * (SROW * 4));
#pragma unroll
            for (int jp = 0; jp < 4; jp++)
                LDSM4(fb[4 * jp], fb[4 * jp + 1], fb[4 * jp + 2], fb[4 * jp + 3],
                      stB + ko + (uint32_t)(jp * 16) * (SROW * 4));

            // round to tf32-nearest in place
#pragma unroll
            for (int q = 0; q < 16; q++) fa[q] += 0x1000u;
#pragma unroll
            for (int q = 0; q < 16; q++) fb[q] += 0x1000u;

#pragma unroll
            for (int i = 0; i < 4; i++)
#pragma unroll
                for (int j = 0; j < 8; j++) {
                    const int jp = j >> 1, jo = j & 1;
                    MMA_TF32(acc[i][j],
                             fa[4 * i], fa[4 * i + 1], fa[4 * i + 2], fa[4 * i + 3],
                             fb[4 * jp + jo], fb[4 * jp + 2 + jo]);
                }
        }
    }

    // ---- epilogue: bias + ReLU, float2 stores ----
    float2 bv[8];
#pragma unroll
    for (int j = 0; j < 8; j++) {
        const int c = colBase + wn * 64 + j * 8 + 2 * tg;
        float2 b = *(const float2*)(bias1 + c);
        if (bias2) {
            float2 b2 = *(const float2*)(bias2 + c);
            b.x += b2.x; b.y += b2.y;
        }
        bv[j] = b;
    }
#pragma unroll
    for (int i = 0; i < 4; i++) {
        const int r0 = rowBase + wm * 64 + i * 16 + g;
#pragma unroll
        for (int j = 0; j < 8; j++) {
            const int c = colBase + wn * 64 + j * 8 + 2 * tg;
            float2 v0, v1;
            v0.x = fmaxf(acc[i][j][0] + bv[j].x, 0.0f);
            v0.y = fmaxf(acc[i][j][1] + bv[j].y, 0.0f);
            v1.x = fmaxf(acc[i][j][2] + bv[j].x, 0.0f);
            v1.y = fmaxf(acc[i][j][3] + bv[j].y, 0.0f);
            *(float2*)&C[(size_t)r0 * ldc + c]       = v0;
            *(float2*)&C[(size_t)(r0 + 8) * ldc + c] = v1;
        }
    }
}

extern "C" void kernel_launch(void* const* d_in, const int* in_sizes, int n_in,
                              void* d_out, int out_size)
{
    (void)in_sizes; (void)n_in; (void)out_size;
    const int B_ = 8192, DIN = 1024, H_ = 4096, DO_ = 1024;

    const float* X     = (const float*)d_in[0];
    const float* state = (const float*)d_in[1];
    const float* W_in  = (const float*)d_in[2];
    const float* b_in  = (const float*)d_in[3];
    const float* W_rec = (const float*)d_in[4];
    const float* b_rec = (const float*)d_in[5];
    const float* W_out = (const float*)d_in[6];
    const float* b_out = (const float*)d_in[7];

    float* out       = (float*)d_out;                     // [B, D_OUT]
    float* new_state = (float*)d_out + (size_t)B_ * DO_;  // [B, H]

    static int inited = 0;
    if (!inited) {
        cudaFuncSetAttribute(rnn_gemm_mma,
                             cudaFuncAttributeMaxDynamicSharedMemorySize, SMEM_BYTES);
        inited = 1;
    }

    // GEMM1+2 fused along K: new_state = ReLU(X@W_in^T + state@W_rec^T + b)
    {
        dim3 grid(H_ / BN, B_ / BM);   // (16, 64)
        rnn_gemm_mma<<<grid, 256, SMEM_BYTES>>>(
            X, DIN, W_in, DIN, DIN / BK,
            state, H_, W_rec, H_, H_ / BK,
            b_in, b_rec, new_state, H_);
    }
    // GEMM3: out = ReLU(new_state@W_out^T + b_out)
    {
        dim3 grid(DO_ / BN, B_ / BM);  // (4, 64)
        rnn_gemm_mma<<<grid, 256, SMEM_BYTES>>>(
            new_state, H_, W_out, H_, H_ / BK,
            nullptr, 0, nullptr, 0, 0,
            b_out, nullptr, out, DO_);
    }
}